// round 3
// baseline (speedup 1.0000x reference)
#include <cuda_runtime.h>
#include <math.h>

// Problem: tensor [8192, 256] fp32.
// out = (adj @ X) where adj = rownorm(cosine_sim(X)).
// Factored: M = X_hat^T X (256x256, SYMMETRIC), s = sum_j x_hat_j (256),
//           out[i] = (x_i @ M) / (x_i . s)   (inv-norm cancels).
// Denominator path in fp64 (row_sum cancellation amplifies rounding).

#define NROWS 8192
#define DDIM  256
#define GCHUNKS 64          // gram K-chunks: 128 rows each
#define SCHUNKS 64          // norm/s blocks: 128 rows each
#define NTILES  10          // upper-triangle 64x64 tiles of the 4x4 tile grid

__device__ float  g_invn[NROWS];
__device__ double g_spart[SCHUNKS][DDIM];
__device__ double g_sd[DDIM];
__device__ float  g_rinv[NROWS];
__device__ float  g_Mpart[GCHUNKS][NTILES][64 * 64];
__device__ float  g_M[DDIM * DDIM];

__device__ const int c_TI[NTILES] = {0,0,0,0,1,1,1,2,2,3};
__device__ const int c_TJ[NTILES] = {0,1,2,3,1,2,3,2,3,3};

// ---------------------------------------------------------------------------
// Kernel 1: per-row inverse norms + fp64 partial column sums of X_hat.
// 64 blocks x 256 threads; block b handles rows [b*128, b*128+128).
// ---------------------------------------------------------------------------
__global__ void k_norm_s(const float* __restrict__ X) {
    __shared__ float invn_sh[128];
    const int row0 = blockIdx.x * 128;
    const int wid  = threadIdx.x >> 5;
    const int lane = threadIdx.x & 31;

    for (int r = wid; r < 128; r += 8) {
        const float4* p = reinterpret_cast<const float4*>(X + (size_t)(row0 + r) * DDIM);
        float ss = 0.f;
        #pragma unroll
        for (int q = 0; q < 2; q++) {
            float4 v = p[lane + q * 32];
            ss += v.x * v.x + v.y * v.y + v.z * v.z + v.w * v.w;
        }
        #pragma unroll
        for (int o = 16; o > 0; o >>= 1) ss += __shfl_xor_sync(0xffffffffu, ss, o);
        if (lane == 0) {
            float inv = 1.0f / fmaxf(sqrtf(ss), 1e-8f);
            invn_sh[r]       = inv;
            g_invn[row0 + r] = inv;
        }
    }
    __syncthreads();

    const int t = threadIdx.x;
    double acc = 0.0;
    #pragma unroll 4
    for (int r = 0; r < 128; r++)
        acc += (double)invn_sh[r] * (double)X[(size_t)(row0 + r) * DDIM + t];
    g_spart[blockIdx.x][t] = acc;
}

// ---------------------------------------------------------------------------
// Kernel 2: partial Gram, upper-triangle tiles only (M is symmetric).
// grid = (64 k-chunks, 10 tiles), 256 threads, 4x4 register tile per thread.
// Tile t covers M[64*TI : +64, 64*TJ : +64]; K = 128 rows per chunk.
// ---------------------------------------------------------------------------
__global__ void k_gram(const float* __restrict__ X) {
    __shared__ float SA[8][64];
    __shared__ float SB[8][64];

    const int c  = blockIdx.x;
    const int t  = blockIdx.y;
    const int ti = c_TI[t];
    const int tj = c_TJ[t];
    const int tx = threadIdx.x & 15;
    const int ty = (threadIdx.x >> 4) & 15;
    const int side = threadIdx.x >> 7;          // warps 0-3 load SA, 4-7 load SB
    const int li   = (threadIdx.x >> 4) & 7;    // stage row 0..7
    const int lf   = threadIdx.x & 15;          // float4 slot 0..15
    const int rowbase = c * 128;
    const int colbase = (side == 0 ? ti : tj) * 64;

    float T[4][4];
    #pragma unroll
    for (int i = 0; i < 4; i++)
        #pragma unroll
        for (int j = 0; j < 4; j++) T[i][j] = 0.f;

    for (int kk = 0; kk < 128; kk += 8) {
        const int gr = rowbase + kk + li;
        float4 v = *reinterpret_cast<const float4*>(X + (size_t)gr * DDIM + colbase + lf * 4);
        float scale = (side == 0) ? g_invn[gr] : 1.0f;
        __syncthreads();   // previous iteration's smem reads done
        if (side == 0)
            *reinterpret_cast<float4*>(&SA[li][lf * 4]) =
                make_float4(v.x * scale, v.y * scale, v.z * scale, v.w * scale);
        else
            *reinterpret_cast<float4*>(&SB[li][lf * 4]) = v;
        __syncthreads();
        #pragma unroll
        for (int r = 0; r < 8; r++) {
            float4 a = *reinterpret_cast<const float4*>(&SA[r][ty * 4]);
            float4 b = *reinterpret_cast<const float4*>(&SB[r][tx * 4]);
            const float aa[4] = {a.x, a.y, a.z, a.w};
            const float bb[4] = {b.x, b.y, b.z, b.w};
            #pragma unroll
            for (int i = 0; i < 4; i++)
                #pragma unroll
                for (int j = 0; j < 4; j++) T[i][j] += aa[i] * bb[j];
        }
    }

    float* out = &g_Mpart[c][t][0];
    #pragma unroll
    for (int i = 0; i < 4; i++)
        *reinterpret_cast<float4*>(&out[(ty * 4 + i) * 64 + tx * 4]) =
            make_float4(T[i][0], T[i][1], T[i][2], T[i][3]);
}

// ---------------------------------------------------------------------------
// Kernel 3: fp64 reduce of Mpart (with symmetric mirror) and s-partials.
// 160 blocks x 256 threads cover 10*4096 upper-tile elements.
// ---------------------------------------------------------------------------
__global__ void k_reduce() {
    const int idx = blockIdx.x * 256 + threadIdx.x;   // 0..40959
    const int t = idx >> 12;
    const int e = idx & 4095;
    double acc = 0.0;
    #pragma unroll
    for (int c = 0; c < GCHUNKS; c++) acc += (double)g_Mpart[c][t][e];
    const int k = c_TI[t] * 64 + (e >> 6);
    const int l = c_TJ[t] * 64 + (e & 63);
    const float v = (float)acc;
    if (k < l) {
        g_M[k * DDIM + l] = v;
        g_M[l * DDIM + k] = v;
    } else if (k == l) {
        g_M[k * DDIM + l] = v;
    } // k > l only inside diagonal tiles: skip (mirror writes it)

    if (blockIdx.x == 0) {
        double sa = 0.0;
        #pragma unroll
        for (int b = 0; b < SCHUNKS; b++) sa += g_spart[b][threadIdx.x];
        g_sd[threadIdx.x] = sa;
    }
}

// ---------------------------------------------------------------------------
// Kernel 4: per-row reciprocal denominator rinv[i] = 1 / (x_i . s), fp64.
// 64 blocks x 256 threads.
// ---------------------------------------------------------------------------
__global__ void k_rinv(const float* __restrict__ X) {
    __shared__ double s_sh[DDIM];
    s_sh[threadIdx.x] = g_sd[threadIdx.x];
    __syncthreads();
    const int row0 = blockIdx.x * 128;
    const int wid  = threadIdx.x >> 5;
    const int lane = threadIdx.x & 31;
    for (int r = wid; r < 128; r += 8) {
        const float* xp = X + (size_t)(row0 + r) * DDIM;
        double dp = 0.0;
        #pragma unroll
        for (int q = 0; q < 8; q++) {
            const int k = q * 32 + lane;
            dp += (double)xp[k] * s_sh[k];
        }
        #pragma unroll
        for (int o = 16; o > 0; o >>= 1) dp += __shfl_xor_sync(0xffffffffu, dp, o);
        if (lane == 0) g_rinv[row0 + r] = (float)(1.0 / dp);
    }
}

// ---------------------------------------------------------------------------
// Kernel 5: OUT = (X @ M) * rinv rowwise.
// grid = (128 row tiles, 4 col tiles) = 512 blocks, 256 threads, 4x4/thread.
// SA transposed [k][row] with stride 68 (4*68 % 32banks == 16 -> store halves
// land in disjoint bank sets).
// ---------------------------------------------------------------------------
__global__ void k_out(const float* __restrict__ X, float* __restrict__ OUT) {
    __shared__ float SA[8][68];
    __shared__ float SB[8][64];

    const int row0 = blockIdx.x * 64;
    const int c0   = blockIdx.y * 64;
    const int tx   = threadIdx.x & 15;
    const int ty   = (threadIdx.x >> 4) & 15;

    // loader roles
    const int ar = threadIdx.x >> 1;          // SA: row 0..127 -> only <64 used via tid<128
    const int ah = threadIdx.x & 1;           // SA: k-half
    const int bi = (threadIdx.x >> 4) & 7;    // SB: stage row
    const int bf = threadIdx.x & 15;          // SB: float4 slot

    float T[4][4];
    #pragma unroll
    for (int i = 0; i < 4; i++)
        #pragma unroll
        for (int j = 0; j < 4; j++) T[i][j] = 0.f;

    for (int k0 = 0; k0 < DDIM; k0 += 8) {
        float4 v;
        if (threadIdx.x < 128)
            v = *reinterpret_cast<const float4*>(X + (size_t)(row0 + ar) * DDIM + k0 + ah * 4);
        else
            v = *reinterpret_cast<const float4*>(&g_M[(k0 + bi) * DDIM + c0 + bf * 4]);
        __syncthreads();
        if (threadIdx.x < 128) {
            SA[ah * 4 + 0][ar] = v.x;
            SA[ah * 4 + 1][ar] = v.y;
            SA[ah * 4 + 2][ar] = v.z;
            SA[ah * 4 + 3][ar] = v.w;
        } else {
            *reinterpret_cast<float4*>(&SB[bi][bf * 4]) = v;
        }
        __syncthreads();
        #pragma unroll
        for (int r = 0; r < 8; r++) {
            float4 a = *reinterpret_cast<const float4*>(&SA[r][ty * 4]);
            float4 b = *reinterpret_cast<const float4*>(&SB[r][tx * 4]);
            const float aa[4] = {a.x, a.y, a.z, a.w};
            const float bb[4] = {b.x, b.y, b.z, b.w};
            #pragma unroll
            for (int i = 0; i < 4; i++)
                #pragma unroll
                for (int j = 0; j < 4; j++) T[i][j] += aa[i] * bb[j];
        }
    }

    #pragma unroll
    for (int i = 0; i < 4; i++) {
        const int m = row0 + ty * 4 + i;
        const float rv = g_rinv[m];
        *reinterpret_cast<float4*>(&OUT[(size_t)m * DDIM + c0 + tx * 4]) =
            make_float4(T[i][0] * rv, T[i][1] * rv, T[i][2] * rv, T[i][3] * rv);
    }
}

extern "C" void kernel_launch(void* const* d_in, const int* in_sizes, int n_in,
                              void* d_out, int out_size) {
    (void)in_sizes; (void)n_in; (void)out_size;
    const float* X = (const float*)d_in[0];
    float* OUT     = (float*)d_out;

    k_norm_s<<<SCHUNKS, 256>>>(X);
    k_gram<<<dim3(GCHUNKS, NTILES), 256>>>(X);
    k_reduce<<<160, 256>>>();
    k_rinv<<<64, 256>>>(X);
    k_out<<<dim3(128, 4), 256>>>(X, OUT);
}

// round 4
// speedup vs baseline: 1.5966x; 1.5966x over previous
#include <cuda_runtime.h>
#include <math.h>

// Problem: tensor [8192, 256] fp32.
// out = (adj @ X) where adj = rownorm(cosine_sim(X)).
// Factored: M = X_hat^T X (256x256, SYMMETRIC), s = sum_j x_hat_j (256),
//           out[i] = (x_i @ M) / (x_i . s)   (inv-norm cancels).
// Denominator needs ~fp64 accuracy (row_sum cancellation, min |row_sum|~0.01),
// but B300 vector FP64 is de-rated -> use error-free fp32 transforms (Dot2).

#define NROWS 8192
#define DDIM  256
#define GCHUNKS 64          // gram K-chunks: 128 rows each
#define SCHUNKS 64          // norm/s blocks: 128 rows each
#define NTILES  10          // upper-triangle 64x64 tiles of the 4x4 tile grid

__device__ float  g_invn[NROWS];
__device__ float2 g_spart[SCHUNKS][DDIM];   // compensated fp32 pairs (hi, lo)
__device__ float2 g_s2[DDIM];
__device__ float  g_rinv[NROWS];
__device__ float  g_Mpart[GCHUNKS][NTILES][64 * 64];
__device__ float  g_M[DDIM * DDIM];

__device__ const int c_TI[NTILES] = {0,0,0,0,1,1,1,2,2,3};
__device__ const int c_TJ[NTILES] = {0,1,2,3,1,2,3,2,3,3};

// ---- error-free fp32 transforms ------------------------------------------
__device__ __forceinline__ void twoSum(float a, float b, float& s, float& e) {
    s = a + b;
    float bb = s - a;
    e = (a - (s - bb)) + (b - bb);
}
__device__ __forceinline__ void twoProd(float a, float b, float& p, float& e) {
    p = a * b;
    e = fmaf(a, b, -p);
}

// ---------------------------------------------------------------------------
// Kernel 1: per-row inverse norms + compensated fp32 partial column sums of
// X_hat. 64 blocks x 256 threads; block b handles rows [b*128, +128).
// ---------------------------------------------------------------------------
__global__ void k_norm_s(const float* __restrict__ X) {
    __shared__ float invn_sh[128];
    const int row0 = blockIdx.x * 128;
    const int wid  = threadIdx.x >> 5;
    const int lane = threadIdx.x & 31;

    for (int r = wid; r < 128; r += 8) {
        const float4* p = reinterpret_cast<const float4*>(X + (size_t)(row0 + r) * DDIM);
        float ss = 0.f;
        #pragma unroll
        for (int q = 0; q < 2; q++) {
            float4 v = p[lane + q * 32];
            ss += v.x * v.x + v.y * v.y + v.z * v.z + v.w * v.w;
        }
        #pragma unroll
        for (int o = 16; o > 0; o >>= 1) ss += __shfl_xor_sync(0xffffffffu, ss, o);
        if (lane == 0) {
            float inv = 1.0f / fmaxf(sqrtf(ss), 1e-8f);
            invn_sh[r]       = inv;
            g_invn[row0 + r] = inv;
        }
    }
    __syncthreads();

    // Dot2 column sum: thread t owns column t (coalesced across threads).
    const int t = threadIdx.x;
    float s = 0.f, c = 0.f;
    #pragma unroll 4
    for (int r = 0; r < 128; r++) {
        float p, e, t1;
        twoProd(invn_sh[r], X[(size_t)(row0 + r) * DDIM + t], p, e);
        twoSum(s, p, s, t1);
        c += t1 + e;
    }
    g_spart[blockIdx.x][t] = make_float2(s, c);
}

// ---------------------------------------------------------------------------
// Kernel 2: partial Gram, upper-triangle tiles only (M is symmetric).
// grid = (64 k-chunks, 10 tiles), 256 threads, 4x4 register tile per thread.
// ---------------------------------------------------------------------------
__global__ void k_gram(const float* __restrict__ X) {
    __shared__ float SA[8][64];
    __shared__ float SB[8][64];

    const int c  = blockIdx.x;
    const int t  = blockIdx.y;
    const int ti = c_TI[t];
    const int tj = c_TJ[t];
    const int tx = threadIdx.x & 15;
    const int ty = (threadIdx.x >> 4) & 15;
    const int side = threadIdx.x >> 7;          // warps 0-3 load SA, 4-7 load SB
    const int li   = (threadIdx.x >> 4) & 7;    // stage row 0..7
    const int lf   = threadIdx.x & 15;          // float4 slot 0..15
    const int rowbase = c * 128;
    const int colbase = (side == 0 ? ti : tj) * 64;

    float T[4][4];
    #pragma unroll
    for (int i = 0; i < 4; i++)
        #pragma unroll
        for (int j = 0; j < 4; j++) T[i][j] = 0.f;

    for (int kk = 0; kk < 128; kk += 8) {
        const int gr = rowbase + kk + li;
        float4 v = *reinterpret_cast<const float4*>(X + (size_t)gr * DDIM + colbase + lf * 4);
        float scale = (side == 0) ? g_invn[gr] : 1.0f;
        __syncthreads();   // previous iteration's smem reads done
        if (side == 0)
            *reinterpret_cast<float4*>(&SA[li][lf * 4]) =
                make_float4(v.x * scale, v.y * scale, v.z * scale, v.w * scale);
        else
            *reinterpret_cast<float4*>(&SB[li][lf * 4]) = v;
        __syncthreads();
        #pragma unroll
        for (int r = 0; r < 8; r++) {
            float4 a = *reinterpret_cast<const float4*>(&SA[r][ty * 4]);
            float4 b = *reinterpret_cast<const float4*>(&SB[r][tx * 4]);
            const float aa[4] = {a.x, a.y, a.z, a.w};
            const float bb[4] = {b.x, b.y, b.z, b.w};
            #pragma unroll
            for (int i = 0; i < 4; i++)
                #pragma unroll
                for (int j = 0; j < 4; j++) T[i][j] += aa[i] * bb[j];
        }
    }

    float* out = &g_Mpart[c][t][0];
    #pragma unroll
    for (int i = 0; i < 4; i++)
        *reinterpret_cast<float4*>(&out[(ty * 4 + i) * 64 + tx * 4]) =
            make_float4(T[i][0], T[i][1], T[i][2], T[i][3]);
}

// ---------------------------------------------------------------------------
// Kernel 3: compensated fp32 reduce of Mpart (with symmetric mirror) and the
// s-partial pairs. 160 blocks x 256 threads cover 10*4096 upper-tile elems.
// ---------------------------------------------------------------------------
__global__ void k_reduce() {
    const int idx = blockIdx.x * 256 + threadIdx.x;   // 0..40959
    const int t = idx >> 12;
    const int e = idx & 4095;
    float s = 0.f, comp = 0.f;
    #pragma unroll
    for (int c = 0; c < GCHUNKS; c++) {
        float t1;
        twoSum(s, g_Mpart[c][t][e], s, t1);
        comp += t1;
    }
    const float v = s + comp;
    const int k = c_TI[t] * 64 + (e >> 6);
    const int l = c_TJ[t] * 64 + (e & 63);
    if (k < l) {
        g_M[k * DDIM + l] = v;
        g_M[l * DDIM + k] = v;
    } else if (k == l) {
        g_M[k * DDIM + l] = v;
    } // k > l only inside diagonal tiles: mirror writes it

    if (blockIdx.x == 0) {
        float sa = 0.f, ca = 0.f;
        #pragma unroll
        for (int b = 0; b < SCHUNKS; b++) {
            float2 p = g_spart[b][threadIdx.x];
            float t1;
            twoSum(sa, p.x, sa, t1);
            ca += t1 + p.y;
        }
        g_s2[threadIdx.x] = make_float2(sa, ca);
    }
}

// ---------------------------------------------------------------------------
// Kernel 4: rinv[i] = 1 / (x_i . s) via fp32 Dot2 (s kept as hi+lo pair).
// 64 blocks x 256 threads, 8 warps x 16 rows.
// ---------------------------------------------------------------------------
__global__ void k_rinv(const float* __restrict__ X) {
    __shared__ float2 s_sh[DDIM];
    s_sh[threadIdx.x] = g_s2[threadIdx.x];
    __syncthreads();
    const int row0 = blockIdx.x * 128;
    const int wid  = threadIdx.x >> 5;
    const int lane = threadIdx.x & 31;
    for (int r = wid; r < 128; r += 8) {
        const float* xp = X + (size_t)(row0 + r) * DDIM;
        float s = 0.f, c = 0.f;
        #pragma unroll
        for (int q = 0; q < 8; q++) {
            const int k = q * 32 + lane;
            const float x = xp[k];
            const float2 sv = s_sh[k];
            float p, e, t1;
            twoProd(x, sv.x, p, e);
            e = fmaf(x, sv.y, e);
            twoSum(s, p, s, t1);
            c += t1 + e;
        }
        #pragma unroll
        for (int o = 16; o > 0; o >>= 1) {
            float s2 = __shfl_xor_sync(0xffffffffu, s, o);
            float c2 = __shfl_xor_sync(0xffffffffu, c, o);
            float t1;
            twoSum(s, s2, s, t1);
            c += c2 + t1;
        }
        if (lane == 0) {
            double den = (double)s + (double)c;
            g_rinv[row0 + r] = (float)(1.0 / den);
        }
    }
}

// ---------------------------------------------------------------------------
// Kernel 5: OUT = (X @ M) * rinv rowwise.
// grid = (128 row tiles, 4 col tiles) = 512 blocks, 256 threads, 4x4/thread.
// ---------------------------------------------------------------------------
__global__ void k_out(const float* __restrict__ X, float* __restrict__ OUT) {
    __shared__ float SA[8][68];
    __shared__ float SB[8][64];

    const int row0 = blockIdx.x * 64;
    const int c0   = blockIdx.y * 64;
    const int tx   = threadIdx.x & 15;
    const int ty   = (threadIdx.x >> 4) & 15;

    const int ar = threadIdx.x >> 1;          // SA loader: row (tid<128)
    const int ah = threadIdx.x & 1;           // SA loader: k-half
    const int bi = (threadIdx.x >> 4) & 7;    // SB loader: stage row
    const int bf = threadIdx.x & 15;          // SB loader: float4 slot

    float T[4][4];
    #pragma unroll
    for (int i = 0; i < 4; i++)
        #pragma unroll
        for (int j = 0; j < 4; j++) T[i][j] = 0.f;

    for (int k0 = 0; k0 < DDIM; k0 += 8) {
        float4 v;
        if (threadIdx.x < 128)
            v = *reinterpret_cast<const float4*>(X + (size_t)(row0 + ar) * DDIM + k0 + ah * 4);
        else
            v = *reinterpret_cast<const float4*>(&g_M[(k0 + bi) * DDIM + c0 + bf * 4]);
        __syncthreads();
        if (threadIdx.x < 128) {
            SA[ah * 4 + 0][ar] = v.x;
            SA[ah * 4 + 1][ar] = v.y;
            SA[ah * 4 + 2][ar] = v.z;
            SA[ah * 4 + 3][ar] = v.w;
        } else {
            *reinterpret_cast<float4*>(&SB[bi][bf * 4]) = v;
        }
        __syncthreads();
        #pragma unroll
        for (int r = 0; r < 8; r++) {
            float4 a = *reinterpret_cast<const float4*>(&SA[r][ty * 4]);
            float4 b = *reinterpret_cast<const float4*>(&SB[r][tx * 4]);
            const float aa[4] = {a.x, a.y, a.z, a.w};
            const float bb[4] = {b.x, b.y, b.z, b.w};
            #pragma unroll
            for (int i = 0; i < 4; i++)
                #pragma unroll
                for (int j = 0; j < 4; j++) T[i][j] += aa[i] * bb[j];
        }
    }

    #pragma unroll
    for (int i = 0; i < 4; i++) {
        const int m = row0 + ty * 4 + i;
        const float rv = g_rinv[m];
        *reinterpret_cast<float4*>(&OUT[(size_t)m * DDIM + c0 + tx * 4]) =
            make_float4(T[i][0] * rv, T[i][1] * rv, T[i][2] * rv, T[i][3] * rv);
    }
}

extern "C" void kernel_launch(void* const* d_in, const int* in_sizes, int n_in,
                              void* d_out, int out_size) {
    (void)in_sizes; (void)n_in; (void)out_size;
    const float* X = (const float*)d_in[0];
    float* OUT     = (float*)d_out;

    k_norm_s<<<SCHUNKS, 256>>>(X);
    k_gram<<<dim3(GCHUNKS, NTILES), 256>>>(X);
    k_reduce<<<160, 256>>>();
    k_rinv<<<64, 256>>>(X);
    k_out<<<dim3(128, 4), 256>>>(X, OUT);
}

// round 5
// speedup vs baseline: 1.7145x; 1.0739x over previous
#include <cuda_runtime.h>
#include <math.h>

// Problem: tensor [8192, 256] fp32.
// out = (adj @ X) where adj = rownorm(cosine_sim(X)).
// Factored: M = X_hat^T X (256x256, SYMMETRIC), s = sum_j x_hat_j (256),
//           out[i] = (x_i @ M) / (x_i . s)   (inv-norm cancels).
// Denominator needs ~fp64 accuracy (row_sum cancellation, min |row_sum|~0.01);
// B300 vector FP64 is de-rated -> error-free fp32 transforms (Dot2).

#define NROWS 8192
#define DDIM  256
#define GCHUNKS 64          // gram K-chunks: 128 rows each
#define SCHUNKS 256         // norm/s blocks: 32 rows each
#define NTILES  10          // upper-triangle 64x64 tiles of the 4x4 tile grid

__device__ float  g_invn[NROWS];
__device__ float2 g_spart[SCHUNKS][DDIM];   // compensated fp32 pairs (hi, lo)
__device__ float2 g_s2[DDIM];
__device__ float  g_rinv[NROWS];
__device__ float  g_Mpart[GCHUNKS][NTILES][64 * 64];
__device__ float  g_M[DDIM * DDIM];

__device__ const int c_TI[NTILES] = {0,0,0,0,1,1,1,2,2,3};
__device__ const int c_TJ[NTILES] = {0,1,2,3,1,2,3,2,3,3};

// ---- error-free fp32 transforms ------------------------------------------
__device__ __forceinline__ void twoSum(float a, float b, float& s, float& e) {
    s = a + b;
    float bb = s - a;
    e = (a - (s - bb)) + (b - bb);
}
__device__ __forceinline__ void twoProd(float a, float b, float& p, float& e) {
    p = a * b;
    e = fmaf(a, b, -p);
}

// ---------------------------------------------------------------------------
// Kernel 1: per-row inverse norms + compensated fp32 partial column sums of
// X_hat. 256 blocks x 256 threads; block b handles rows [b*32, +32).
// ---------------------------------------------------------------------------
__global__ void __launch_bounds__(256) k_norm_s(const float* __restrict__ X) {
    __shared__ float invn_sh[32];
    const int row0 = blockIdx.x * 32;
    const int wid  = threadIdx.x >> 5;
    const int lane = threadIdx.x & 31;

    // 8 warps x 4 rows: warp-level sum of squares per row.
    for (int r = wid; r < 32; r += 8) {
        const float4* p = reinterpret_cast<const float4*>(X + (size_t)(row0 + r) * DDIM);
        float ss = 0.f;
        #pragma unroll
        for (int q = 0; q < 2; q++) {
            float4 v = p[lane + q * 32];
            ss += v.x * v.x + v.y * v.y + v.z * v.z + v.w * v.w;
        }
        #pragma unroll
        for (int o = 16; o > 0; o >>= 1) ss += __shfl_xor_sync(0xffffffffu, ss, o);
        if (lane == 0) {
            float inv = 1.0f / fmaxf(sqrtf(ss), 1e-8f);
            invn_sh[r]       = inv;
            g_invn[row0 + r] = inv;
        }
    }
    __syncthreads();

    // Dot2 column sum over 32 rows: thread t owns column t (coalesced).
    const int t = threadIdx.x;
    float s = 0.f, c = 0.f;
    #pragma unroll
    for (int r = 0; r < 32; r++) {
        float p, e, t1;
        twoProd(invn_sh[r], X[(size_t)(row0 + r) * DDIM + t], p, e);
        twoSum(s, p, s, t1);
        c += t1 + e;
    }
    g_spart[blockIdx.x][t] = make_float2(s, c);
}

// ---------------------------------------------------------------------------
// Kernel 2: partial Gram, upper-triangle tiles only (M is symmetric).
// grid = (64 k-chunks, 10 tiles), 256 threads, 4x4 register tile per thread.
// ---------------------------------------------------------------------------
__global__ void __launch_bounds__(256) k_gram(const float* __restrict__ X) {
    __shared__ float SA[8][64];
    __shared__ float SB[8][64];

    const int c  = blockIdx.x;
    const int t  = blockIdx.y;
    const int ti = c_TI[t];
    const int tj = c_TJ[t];
    const int tx = threadIdx.x & 15;
    const int ty = (threadIdx.x >> 4) & 15;
    const int side = threadIdx.x >> 7;          // warps 0-3 load SA, 4-7 load SB
    const int li   = (threadIdx.x >> 4) & 7;    // stage row 0..7
    const int lf   = threadIdx.x & 15;          // float4 slot 0..15
    const int rowbase = c * 128;
    const int colbase = (side == 0 ? ti : tj) * 64;

    float T[4][4];
    #pragma unroll
    for (int i = 0; i < 4; i++)
        #pragma unroll
        for (int j = 0; j < 4; j++) T[i][j] = 0.f;

    for (int kk = 0; kk < 128; kk += 8) {
        const int gr = rowbase + kk + li;
        float4 v = *reinterpret_cast<const float4*>(X + (size_t)gr * DDIM + colbase + lf * 4);
        float scale = (side == 0) ? g_invn[gr] : 1.0f;
        __syncthreads();   // previous iteration's smem reads done
        if (side == 0)
            *reinterpret_cast<float4*>(&SA[li][lf * 4]) =
                make_float4(v.x * scale, v.y * scale, v.z * scale, v.w * scale);
        else
            *reinterpret_cast<float4*>(&SB[li][lf * 4]) = v;
        __syncthreads();
        #pragma unroll
        for (int r = 0; r < 8; r++) {
            float4 a = *reinterpret_cast<const float4*>(&SA[r][ty * 4]);
            float4 b = *reinterpret_cast<const float4*>(&SB[r][tx * 4]);
            const float aa[4] = {a.x, a.y, a.z, a.w};
            const float bb[4] = {b.x, b.y, b.z, b.w};
            #pragma unroll
            for (int i = 0; i < 4; i++)
                #pragma unroll
                for (int j = 0; j < 4; j++) T[i][j] += aa[i] * bb[j];
        }
    }

    float* out = &g_Mpart[c][t][0];
    #pragma unroll
    for (int i = 0; i < 4; i++)
        *reinterpret_cast<float4*>(&out[(ty * 4 + i) * 64 + tx * 4]) =
            make_float4(T[i][0], T[i][1], T[i][2], T[i][3]);
}

// ---------------------------------------------------------------------------
// Kernel 3: compensated fp32 reduce of Mpart (with symmetric mirror) and the
// s-partial pairs. 160 blocks x 256 threads cover 10*4096 upper-tile elems.
// ---------------------------------------------------------------------------
__global__ void __launch_bounds__(256) k_reduce() {
    const int idx = blockIdx.x * 256 + threadIdx.x;   // 0..40959
    const int t = idx >> 12;
    const int e = idx & 4095;
    float s = 0.f, comp = 0.f;
    #pragma unroll
    for (int c = 0; c < GCHUNKS; c++) {
        float t1;
        twoSum(s, g_Mpart[c][t][e], s, t1);
        comp += t1;
    }
    const float v = s + comp;
    const int k = c_TI[t] * 64 + (e >> 6);
    const int l = c_TJ[t] * 64 + (e & 63);
    if (k < l) {
        g_M[k * DDIM + l] = v;
        g_M[l * DDIM + k] = v;
    } else if (k == l) {
        g_M[k * DDIM + l] = v;
    } // k > l only inside diagonal tiles: mirror writes it

    if (blockIdx.x == 0) {
        float sa = 0.f, ca = 0.f;
        #pragma unroll 8
        for (int b = 0; b < SCHUNKS; b++) {
            float2 p = g_spart[b][threadIdx.x];
            float t1;
            twoSum(sa, p.x, sa, t1);
            ca += t1 + p.y;
        }
        g_s2[threadIdx.x] = make_float2(sa, ca);
    }
}

// ---------------------------------------------------------------------------
// Kernel 4: rinv[i] = 1 / (x_i . s) via fp32 Dot2, ONE ROW PER WARP.
// 1024 blocks x 256 threads (8 warps): warp w of block b owns row b*8+w.
// ---------------------------------------------------------------------------
__global__ void __launch_bounds__(256) k_rinv(const float* __restrict__ X) {
    __shared__ float2 s_sh[DDIM];
    s_sh[threadIdx.x] = g_s2[threadIdx.x];
    __syncthreads();
    const int wid  = threadIdx.x >> 5;
    const int lane = threadIdx.x & 31;
    const int row  = blockIdx.x * 8 + wid;

    const float* xp = X + (size_t)row * DDIM;
    float s = 0.f, c = 0.f;
    #pragma unroll
    for (int q = 0; q < 8; q++) {
        const int k = q * 32 + lane;
        const float x = xp[k];
        const float2 sv = s_sh[k];
        float p, e, t1;
        twoProd(x, sv.x, p, e);
        e = fmaf(x, sv.y, e);
        twoSum(s, p, s, t1);
        c += t1 + e;
    }
    #pragma unroll
    for (int o = 16; o > 0; o >>= 1) {
        float s2 = __shfl_xor_sync(0xffffffffu, s, o);
        float c2 = __shfl_xor_sync(0xffffffffu, c, o);
        float t1;
        twoSum(s, s2, s, t1);
        c += c2 + t1;
    }
    if (lane == 0) {
        double den = (double)s + (double)c;
        g_rinv[row] = (float)(1.0 / den);
    }
}

// ---------------------------------------------------------------------------
// Kernel 5: OUT = (X @ M) * rinv rowwise.
// grid = (128 row tiles, 4 col tiles) = 512 blocks, 256 threads, 4x4/thread.
// ---------------------------------------------------------------------------
__global__ void __launch_bounds__(256) k_out(const float* __restrict__ X,
                                             float* __restrict__ OUT) {
    __shared__ float SA[8][68];
    __shared__ float SB[8][64];

    const int row0 = blockIdx.x * 64;
    const int c0   = blockIdx.y * 64;
    const int tx   = threadIdx.x & 15;
    const int ty   = (threadIdx.x >> 4) & 15;

    const int ar = threadIdx.x >> 1;          // SA loader: row (tid<128)
    const int ah = threadIdx.x & 1;           // SA loader: k-half
    const int bi = (threadIdx.x >> 4) & 7;    // SB loader: stage row
    const int bf = threadIdx.x & 15;          // SB loader: float4 slot

    float T[4][4];
    #pragma unroll
    for (int i = 0; i < 4; i++)
        #pragma unroll
        for (int j = 0; j < 4; j++) T[i][j] = 0.f;

    for (int k0 = 0; k0 < DDIM; k0 += 8) {
        float4 v;
        if (threadIdx.x < 128)
            v = *reinterpret_cast<const float4*>(X + (size_t)(row0 + ar) * DDIM + k0 + ah * 4);
        else
            v = *reinterpret_cast<const float4*>(&g_M[(k0 + bi) * DDIM + c0 + bf * 4]);
        __syncthreads();
        if (threadIdx.x < 128) {
            SA[ah * 4 + 0][ar] = v.x;
            SA[ah * 4 + 1][ar] = v.y;
            SA[ah * 4 + 2][ar] = v.z;
            SA[ah * 4 + 3][ar] = v.w;
        } else {
            *reinterpret_cast<float4*>(&SB[bi][bf * 4]) = v;
        }
        __syncthreads();
        #pragma unroll
        for (int r = 0; r < 8; r++) {
            float4 a = *reinterpret_cast<const float4*>(&SA[r][ty * 4]);
            float4 b = *reinterpret_cast<const float4*>(&SB[r][tx * 4]);
            const float aa[4] = {a.x, a.y, a.z, a.w};
            const float bb[4] = {b.x, b.y, b.z, b.w};
            #pragma unroll
            for (int i = 0; i < 4; i++)
                #pragma unroll
                for (int j = 0; j < 4; j++) T[i][j] += aa[i] * bb[j];
        }
    }

    #pragma unroll
    for (int i = 0; i < 4; i++) {
        const int m = row0 + ty * 4 + i;
        const float rv = g_rinv[m];
        *reinterpret_cast<float4*>(&OUT[(size_t)m * DDIM + c0 + tx * 4]) =
            make_float4(T[i][0] * rv, T[i][1] * rv, T[i][2] * rv, T[i][3] * rv);
    }
}

extern "C" void kernel_launch(void* const* d_in, const int* in_sizes, int n_in,
                              void* d_out, int out_size) {
    (void)in_sizes; (void)n_in; (void)out_size;
    const float* X = (const float*)d_in[0];
    float* OUT     = (float*)d_out;

    k_norm_s<<<SCHUNKS, 256>>>(X);
    k_gram<<<dim3(GCHUNKS, NTILES), 256>>>(X);
    k_reduce<<<160, 256>>>();
    k_rinv<<<1024, 256>>>(X);
    k_out<<<dim3(128, 4), 256>>>(X, OUT);
}